// round 16
// baseline (speedup 1.0000x reference)
#include <cuda_runtime.h>
#include <cuda_bf16.h>
#include <stdint.h>

// Fused gather-concat:
//   out[r, 0:8]  = proc_pos[process_ids[r], :]   (16x8 f32 -> smem, transposed)
//   out[r, 8:11] = locs_sp[location_ids[r], :]   (500000x3 f32 -> padded float4 table)
//
// R16: TMA bulk store at BLOCK granularity. R15's per-warp (1408B) bulk
// stores paid fence+commit+wait per 32 rows and regressed; here one
// 11264B bulk store per 256-row block-tile amortizes that overhead 8x while
// keeping the l1tex win (no flush-LDS, no STG). Persistent blocks, double-
// buffered stage slots, R13's 2-stage per-thread id/gather pipeline
// (ids(t+2) prefetch, gather(t+1) issue, stage+flush t), transposed proc
// table, lane-stride-11 STS (conflict-free).

#define THREADS 256
#define PROC_DIM 8
#define SP_DIM 3
#define OUT_DIM 11
#define MAX_LOCS 500000
#define BTILE_BYTES (THREADS * OUT_DIM * 4)   // 11264

__device__ int g_ids_are_i64;
__device__ float4 g_locs_pad[MAX_LOCS];   // 8 MB static scratch

__global__ __launch_bounds__(256)
void setup_kernel(const float* __restrict__ locs_sp, int num_locs,
                  const int* __restrict__ loc_ids_w, int naug)
{
    int i = blockIdx.x * blockDim.x + threadIdx.x;
    if (i < num_locs) {
        const float* s = locs_sp + (size_t)i * SP_DIM;
        float4 v;
        v.x = s[0]; v.y = s[1]; v.z = s[2]; v.w = 0.0f;
        g_locs_pad[i] = v;
    }
    // int64 little-endian ids with values < 5e5 look like (v,0,v,0,...):
    // every odd 32-bit word is zero. Random int32: P(64 zeros) ~ 0.
    if (blockIdx.x == 0) {
        __shared__ int s_not64;
        if (threadIdx.x == 0) s_not64 = 0;
        __syncthreads();
        int n_check = naug < 64 ? naug : 64;
        if (threadIdx.x < n_check) {
            if (loc_ids_w[2 * threadIdx.x + 1] != 0) atomicOr(&s_not64, 1);
        }
        __syncthreads();
        if (threadIdx.x == 0) g_ids_are_i64 = s_not64 ? 0 : 1;
    }
}

// Load ids for one row, clamp, pack: (pid << 20) | lid  (lid < 2^20).
__device__ __forceinline__ int load_ids_packed(
    const void* process_ids, const void* location_ids,
    int row, int naug, int ids64, int num_procs, int num_locs)
{
    int rp = 0, rl = 0;
    if (row < naug) {
        if (ids64) {
            rp = (int)__ldcs(&((const long long*)process_ids)[row]);
            rl = (int)__ldcs(&((const long long*)location_ids)[row]);
        } else {
            rp = __ldcs(&((const int*)process_ids)[row]);
            rl = __ldcs(&((const int*)location_ids)[row]);
        }
    }
    rp = min(max(rp, 0), num_procs - 1);
    rl = min(max(rl, 0), num_locs - 1);
    return (rp << 20) | rl;
}

__global__ __launch_bounds__(THREADS, 8)
void gather_concat_kernel(
    const float* __restrict__ proc_pos,
    const void*  __restrict__ process_ids,
    const void*  __restrict__ location_ids,
    float* __restrict__ out,
    int naug,
    int num_procs,
    int num_locs,
    int nbtiles)
{
    __shared__ float s_procT[PROC_DIM * 64];                        // [c][pid]
    __shared__ __align__(16) float s_stage[2][THREADS * OUT_DIM];   // 2 x 11264 B

    const int tid = threadIdx.x;

    const int proc_elems = num_procs * PROC_DIM;
    for (int i = tid; i < proc_elems; i += THREADS) {
        s_procT[(i % PROC_DIM) * num_procs + (i / PROC_DIM)] = proc_pos[i];
    }
    __syncthreads();

    const int ids64 = g_ids_are_i64;
    const int GB = gridDim.x;               // block-tile stride
    int t = blockIdx.x;
    if (t >= nbtiles) return;

    // Pipeline prologue: ids+gather for tile t, ids for tile t+GB.
    int g = load_ids_packed(process_ids, location_ids, t * THREADS + tid,
                            naug, ids64, num_procs, num_locs);
    float4 v = __ldcg(&g_locs_pad[g & 0xFFFFF]);

    int tn = t + GB;
    int g_n = 0;
    if (tn < nbtiles)
        g_n = load_ids_packed(process_ids, location_ids, tn * THREADS + tid,
                              naug, ids64, num_procs, num_locs);

    int sb = 0;
    while (t < nbtiles) {
        // Next tile's gather (ids resident, clamped index: always safe).
        float4 v_n = __ldcg(&g_locs_pad[g_n & 0xFFFFF]);

        // Ids two tiles ahead.
        const int tnn = tn + GB;
        int g_nn = 0;
        if (tnn < nbtiles)
            g_nn = load_ids_packed(process_ids, location_ids,
                                   tnn * THREADS + tid,
                                   naug, ids64, num_procs, num_locs);

        // Slot sb was bulk-stored 2 iterations ago; allowing 1 outstanding
        // group (last iteration's store of the other slot) guarantees it
        // has finished reading smem.
        if (tid == 0)
            asm volatile("cp.async.bulk.wait_group.read 1;" ::: "memory");
        __syncthreads();

        const int rb = t * THREADS;
        const int pid = g >> 20;
        float* dst = &s_stage[sb][tid * OUT_DIM];

        if (rb + THREADS <= naug) {
            // ---- Full block-tile ----
            #pragma unroll
            for (int c = 0; c < PROC_DIM; c++)
                dst[c] = s_procT[c * num_procs + pid];
            dst[PROC_DIM + 0] = v.x;
            dst[PROC_DIM + 1] = v.y;
            dst[PROC_DIM + 2] = v.z;
            __syncthreads();

            if (tid == 0) {
                asm volatile("fence.proxy.async.shared::cta;" ::: "memory");
                uint32_t s_addr = (uint32_t)__cvta_generic_to_shared(&s_stage[sb][0]);
                unsigned long long g_addr =
                    (unsigned long long)__cvta_generic_to_global(out + (size_t)rb * OUT_DIM);
                asm volatile(
                    "cp.async.bulk.global.shared::cta.bulk_group [%0], [%1], %2;"
                    :: "l"(g_addr), "r"(s_addr), "r"(BTILE_BYTES) : "memory");
                asm volatile("cp.async.bulk.commit_group;" ::: "memory");
            }
        } else {
            // ---- Tail tile (scalar path; last tile for this block) ----
            if (rb + tid < naug) {
                #pragma unroll
                for (int c = 0; c < PROC_DIM; c++)
                    dst[c] = s_procT[c * num_procs + pid];
                dst[PROC_DIM + 0] = v.x;
                dst[PROC_DIM + 1] = v.y;
                dst[PROC_DIM + 2] = v.z;
            }
            __syncthreads();
            const int total = (naug - rb) * OUT_DIM;
            float* o = out + (size_t)rb * OUT_DIM;
            const float* st = &s_stage[sb][0];
            for (int i = tid; i < total; i += THREADS)
                o[i] = st[i];
            __syncthreads();
        }

        // Rotate pipeline.
        g = g_n; v = v_n;
        g_n = g_nn;
        t = tn; tn = tnn;
        sb ^= 1;
    }

    // Drain outstanding bulk stores before exit.
    if (tid == 0)
        asm volatile("cp.async.bulk.wait_group.read 0;" ::: "memory");
}

// Safety fallback for num_locs > MAX_LOCS (not hit for this problem).
__global__ __launch_bounds__(THREADS)
void gather_concat_fallback(
    const float* __restrict__ proc_pos,
    const float* __restrict__ locs_sp,
    const void*  __restrict__ process_ids,
    const void*  __restrict__ location_ids,
    float* __restrict__ out,
    int naug, int num_procs, int num_locs)
{
    const long long row = (long long)blockIdx.x * THREADS + threadIdx.x;
    if (row >= naug) return;
    const int ids64 = g_ids_are_i64;
    long long rp, rl;
    if (ids64) {
        rp = ((const long long*)process_ids)[row];
        rl = ((const long long*)location_ids)[row];
    } else {
        rp = ((const int*)process_ids)[row];
        rl = ((const int*)location_ids)[row];
    }
    int pid = (int)min(max(rp, 0LL), (long long)num_procs - 1);
    long long lid = min(max(rl, 0LL), (long long)num_locs - 1);
    float* o = out + (size_t)row * OUT_DIM;
    #pragma unroll
    for (int c = 0; c < PROC_DIM; c++) o[c] = proc_pos[pid * PROC_DIM + c];
    #pragma unroll
    for (int c = 0; c < SP_DIM; c++)  o[PROC_DIM + c] = locs_sp[lid * SP_DIM + c];
}

extern "C" void kernel_launch(void* const* d_in, const int* in_sizes, int n_in,
                              void* d_out, int out_size) {
    const float* proc_pos     = (const float*)d_in[0];
    const float* locs_sp      = (const float*)d_in[1];
    const void*  process_ids  = d_in[2];
    const void*  location_ids = d_in[3];
    float* out = (float*)d_out;

    const int naug      = in_sizes[2];              // 8,000,000
    const int num_procs = in_sizes[0] / PROC_DIM;   // 16
    const int num_locs  = in_sizes[1] / SP_DIM;     // 500,000

    if (num_locs > MAX_LOCS) {
        setup_kernel<<<1, 256>>>(locs_sp, 0, (const int*)location_ids, naug);
        const long long grid = ((long long)naug + THREADS - 1) / THREADS;
        gather_concat_fallback<<<(int)grid, THREADS>>>(
            proc_pos, locs_sp, process_ids, location_ids, out,
            naug, num_procs, num_locs);
        return;
    }

    {
        const int pg = (num_locs + 255) / 256;
        setup_kernel<<<pg, 256>>>(locs_sp, num_locs,
                                  (const int*)location_ids, naug);
    }

    const int nbtiles = (naug + THREADS - 1) / THREADS;   // 31,250
    int grid = nbtiles < 1216 ? nbtiles : 1216;           // 152 SMs x 8
    gather_concat_kernel<<<grid, THREADS>>>(
        proc_pos, process_ids, location_ids, out,
        naug, num_procs, num_locs, nbtiles);
}

// round 17
// speedup vs baseline: 1.0029x; 1.0029x over previous
#include <cuda_runtime.h>
#include <cuda_bf16.h>
#include <stdint.h>

// Fused gather-concat:
//   out[r, 0:8]  = proc_pos[process_ids[r], :]   (16x8 f32 -> smem, transposed)
//   out[r, 8:11] = locs_sp[location_ids[r], :]   (500000x3 f32 -> padded float4 table)
//
// R17 = R13's proven structure (90.2us: persistent warps, warp-private
// staging, stride-11 STS, float4 __stcs flush, packed ids, id prefetch) with
// 64-row warp tiles: 2 rows per lane per iteration -> 2 independent gathers
// in flight, paired coalesced id loads, half the loop/syncwarp overhead per
// row. Single-stage id prefetch (1-stage == 2-stage at full occ, saves regs).
// TMA store variants (R15/R16) and block-wide barriers (R9) are disproven.

#define THREADS 256
#define WARPS (THREADS / 32)
#define PROC_DIM 8
#define SP_DIM 3
#define OUT_DIM 11
#define MAX_LOCS 500000
#define TILE 64                         // rows per warp iteration (2 per lane)

__device__ int g_ids_are_i64;
__device__ float4 g_locs_pad[MAX_LOCS];   // 8 MB static scratch

__global__ __launch_bounds__(256)
void setup_kernel(const float* __restrict__ locs_sp, int num_locs,
                  const int* __restrict__ loc_ids_w, int naug)
{
    int i = blockIdx.x * blockDim.x + threadIdx.x;
    if (i < num_locs) {
        const float* s = locs_sp + (size_t)i * SP_DIM;
        float4 v;
        v.x = s[0]; v.y = s[1]; v.z = s[2]; v.w = 0.0f;
        g_locs_pad[i] = v;
    }
    // int64 little-endian ids with values < 5e5 look like (v,0,v,0,...):
    // every odd 32-bit word is zero. Random int32: P(64 zeros) ~ 0.
    if (blockIdx.x == 0) {
        __shared__ int s_not64;
        if (threadIdx.x == 0) s_not64 = 0;
        __syncthreads();
        int n_check = naug < 64 ? naug : 64;
        if (threadIdx.x < n_check) {
            if (loc_ids_w[2 * threadIdx.x + 1] != 0) atomicOr(&s_not64, 1);
        }
        __syncthreads();
        if (threadIdx.x == 0) g_ids_are_i64 = s_not64 ? 0 : 1;
    }
}

// Load ids for one row, clamp, pack: (pid << 20) | lid  (lid < 2^20).
__device__ __forceinline__ int load_ids_packed(
    const void* process_ids, const void* location_ids,
    int row, int naug, int ids64, int num_procs, int num_locs)
{
    int rp = 0, rl = 0;
    if (row < naug) {
        if (ids64) {
            rp = (int)__ldcs(&((const long long*)process_ids)[row]);
            rl = (int)__ldcs(&((const long long*)location_ids)[row]);
        } else {
            rp = __ldcs(&((const int*)process_ids)[row]);
            rl = __ldcs(&((const int*)location_ids)[row]);
        }
    }
    rp = min(max(rp, 0), num_procs - 1);
    rl = min(max(rl, 0), num_locs - 1);
    return (rp << 20) | rl;
}

__global__ __launch_bounds__(THREADS)
void gather_concat_kernel(
    const float* __restrict__ proc_pos,
    const void*  __restrict__ process_ids,
    const void*  __restrict__ location_ids,
    float* __restrict__ out,
    int naug,
    int num_procs,
    int num_locs,
    int ntiles)
{
    __shared__ float s_procT[PROC_DIM * 64];             // [c][pid]
    __shared__ float s_stage[WARPS][TILE * OUT_DIM];     // 2816 B / warp

    const int tid  = threadIdx.x;
    const int warp = tid >> 5;
    const int lane = tid & 31;

    const int proc_elems = num_procs * PROC_DIM;
    for (int i = tid; i < proc_elems; i += THREADS) {
        s_procT[(i % PROC_DIM) * num_procs + (i / PROC_DIM)] = proc_pos[i];
    }
    __syncthreads();

    const int ids64 = g_ids_are_i64;
    float* wstage = s_stage[warp];

    const int GW = gridDim.x * WARPS;                    // warp stride (tiles)
    int t = blockIdx.x * WARPS + warp;
    if (t >= ntiles) return;

    // Prologue: ids for tile t (both rows of this lane).
    int g0 = load_ids_packed(process_ids, location_ids, t * TILE + lane,
                             naug, ids64, num_procs, num_locs);
    int g1 = load_ids_packed(process_ids, location_ids, t * TILE + 32 + lane,
                             naug, ids64, num_procs, num_locs);

    while (t < ntiles) {
        // Issue both gathers (ids resident; clamped -> always safe).
        float4 v0 = __ldcg(&g_locs_pad[g0 & 0xFFFFF]);
        float4 v1 = __ldcg(&g_locs_pad[g1 & 0xFFFFF]);

        // Prefetch next tile's ids while gathers are in flight.
        const int tn = t + GW;
        int g0n = 0, g1n = 0;
        if (tn < ntiles) {
            g0n = load_ids_packed(process_ids, location_ids, tn * TILE + lane,
                                  naug, ids64, num_procs, num_locs);
            g1n = load_ids_packed(process_ids, location_ids, tn * TILE + 32 + lane,
                                  naug, ids64, num_procs, num_locs);
        }

        const int rb = t * TILE;
        const int pid0 = g0 >> 20;
        const int pid1 = g1 >> 20;
        float* dst0 = &wstage[lane * OUT_DIM];
        float* dst1 = &wstage[(lane + 32) * OUT_DIM];

        if (rb + TILE <= naug) {
            // ---- Full tile: no per-lane guards ----
            #pragma unroll
            for (int c = 0; c < PROC_DIM; c++)
                dst0[c] = s_procT[c * num_procs + pid0];
            dst0[PROC_DIM + 0] = v0.x;
            dst0[PROC_DIM + 1] = v0.y;
            dst0[PROC_DIM + 2] = v0.z;
            #pragma unroll
            for (int c = 0; c < PROC_DIM; c++)
                dst1[c] = s_procT[c * num_procs + pid1];
            dst1[PROC_DIM + 0] = v1.x;
            dst1[PROC_DIM + 1] = v1.y;
            dst1[PROC_DIM + 2] = v1.z;
            __syncwarp();

            // Flush: 176 contiguous float4 (2816 B, 16B-aligned).
            const float4* s4 = (const float4*)wstage;
            float4* o4 = (float4*)(out + (size_t)rb * OUT_DIM);
            #pragma unroll
            for (int i = lane; i < (TILE * OUT_DIM) / 4; i += 32)
                __stcs(&o4[i], s4[i]);
        } else {
            // ---- Tail tile ----
            if (rb + lane < naug) {
                #pragma unroll
                for (int c = 0; c < PROC_DIM; c++)
                    dst0[c] = s_procT[c * num_procs + pid0];
                dst0[PROC_DIM + 0] = v0.x;
                dst0[PROC_DIM + 1] = v0.y;
                dst0[PROC_DIM + 2] = v0.z;
            }
            if (rb + 32 + lane < naug) {
                #pragma unroll
                for (int c = 0; c < PROC_DIM; c++)
                    dst1[c] = s_procT[c * num_procs + pid1];
                dst1[PROC_DIM + 0] = v1.x;
                dst1[PROC_DIM + 1] = v1.y;
                dst1[PROC_DIM + 2] = v1.z;
            }
            __syncwarp();
            const int total = (naug - rb) * OUT_DIM;
            float* o = out + (size_t)rb * OUT_DIM;
            for (int i = lane; i < total; i += 32)
                o[i] = wstage[i];
        }
        __syncwarp();   // stage buffer reuse barrier

        g0 = g0n; g1 = g1n;
        t = tn;
    }
}

// Safety fallback for num_locs > MAX_LOCS (not hit for this problem).
__global__ __launch_bounds__(THREADS)
void gather_concat_fallback(
    const float* __restrict__ proc_pos,
    const float* __restrict__ locs_sp,
    const void*  __restrict__ process_ids,
    const void*  __restrict__ location_ids,
    float* __restrict__ out,
    int naug, int num_procs, int num_locs)
{
    const long long row = (long long)blockIdx.x * THREADS + threadIdx.x;
    if (row >= naug) return;
    const int ids64 = g_ids_are_i64;
    long long rp, rl;
    if (ids64) {
        rp = ((const long long*)process_ids)[row];
        rl = ((const long long*)location_ids)[row];
    } else {
        rp = ((const int*)process_ids)[row];
        rl = ((const int*)location_ids)[row];
    }
    int pid = (int)min(max(rp, 0LL), (long long)num_procs - 1);
    long long lid = min(max(rl, 0LL), (long long)num_locs - 1);
    float* o = out + (size_t)row * OUT_DIM;
    #pragma unroll
    for (int c = 0; c < PROC_DIM; c++) o[c] = proc_pos[pid * PROC_DIM + c];
    #pragma unroll
    for (int c = 0; c < SP_DIM; c++)  o[PROC_DIM + c] = locs_sp[lid * SP_DIM + c];
}

extern "C" void kernel_launch(void* const* d_in, const int* in_sizes, int n_in,
                              void* d_out, int out_size) {
    const float* proc_pos     = (const float*)d_in[0];
    const float* locs_sp      = (const float*)d_in[1];
    const void*  process_ids  = d_in[2];
    const void*  location_ids = d_in[3];
    float* out = (float*)d_out;

    const int naug      = in_sizes[2];              // 8,000,000
    const int num_procs = in_sizes[0] / PROC_DIM;   // 16
    const int num_locs  = in_sizes[1] / SP_DIM;     // 500,000

    if (num_locs > MAX_LOCS) {
        setup_kernel<<<1, 256>>>(locs_sp, 0, (const int*)location_ids, naug);
        const long long grid = ((long long)naug + THREADS - 1) / THREADS;
        gather_concat_fallback<<<(int)grid, THREADS>>>(
            proc_pos, locs_sp, process_ids, location_ids, out,
            naug, num_procs, num_locs);
        return;
    }

    {
        const int pg = (num_locs + 255) / 256;
        setup_kernel<<<pg, 256>>>(locs_sp, num_locs,
                                  (const int*)location_ids, naug);
    }

    const int ntiles = (naug + TILE - 1) / TILE;    // 125,000
    long long max_blocks = ((long long)ntiles + WARPS - 1) / WARPS;
    int grid = (int)(max_blocks < 1184 ? max_blocks : 1184);
    gather_concat_kernel<<<grid, THREADS>>>(
        proc_pos, process_ids, location_ids, out,
        naug, num_procs, num_locs, ntiles);
}